// round 13
// baseline (speedup 1.0000x reference)
#include <cuda_runtime.h>
#include <cuda_fp16.h>
#include <cstring>
#include <cstdint>

#define N_NODES 5000
#define N_EDGES 30000
#define HID     64
#define ED      16
#define H2      4096
#define NCOLS   262144       // 4096*64 columns of M

#define PASS_NODES 1024
#define N_PASSES   5         // ceil(5000/1024)

// ---------------- static device scratch (no allocs; keep total < ~1.6 GB) ----
// Double-buffered M so gemm(p+1) can overlap stage2(p) on another stream.
__device__ __align__(16) __half g_MA[(size_t)PASS_NODES * NCOLS];  // 536 MB
__device__ __align__(16) __half g_MB[(size_t)PASS_NODES * NCOLS];  // 536 MB
__device__ __align__(16) __half g_hid[(size_t)N_EDGES * H2];       // 246 MB

__device__ int g_off[N_NODES + 1];
__device__ int g_perm[N_EDGES];

// ---------------- fp16 mma (legacy path; tcgen05 rejected: harness PTX
// targets compute_100 without the 'a' feature set) ----------------
__device__ __forceinline__ void mma_f16_k16(float* c,
                                            uint32_t a0, uint32_t a1,
                                            uint32_t a2, uint32_t a3,
                                            uint32_t b0, uint32_t b1) {
    asm volatile(
        "mma.sync.aligned.m16n8k16.row.col.f32.f16.f16.f32 "
        "{%0,%1,%2,%3},{%4,%5,%6,%7},{%8,%9},{%0,%1,%2,%3};"
        : "+f"(c[0]), "+f"(c[1]), "+f"(c[2]), "+f"(c[3])
        : "r"(a0), "r"(a1), "r"(a2), "r"(a3), "r"(b0), "r"(b1));
}

// ---------------- fused single-block CSR build ----------------
__global__ void __launch_bounds__(1024) k_csr(const int* __restrict__ ei) {
    __shared__ int scnt[N_NODES];
    __shared__ int ts[1024];
    int t = threadIdx.x;

    for (int i = t; i < N_NODES; i += 1024) scnt[i] = 0;
    __syncthreads();
    for (int e = t; e < N_EDGES; e += 1024) atomicAdd(&scnt[ei[e]], 1);
    __syncthreads();

    int c[5];
    int base = t * 5;
    int s = 0;
#pragma unroll
    for (int u = 0; u < 5; u++) {
        int id = base + u;
        c[u] = (id < N_NODES) ? scnt[id] : 0;
        s += c[u];
    }
    ts[t] = s;
    __syncthreads();
    for (int ofs = 1; ofs < 1024; ofs <<= 1) {
        int v = (t >= ofs) ? ts[t - ofs] : 0;
        __syncthreads();
        ts[t] += v;
        __syncthreads();
    }
    int ex = ts[t] - s;
#pragma unroll
    for (int u = 0; u < 5; u++) {
        int id = base + u;
        if (id < N_NODES) { g_off[id] = ex; scnt[id] = ex; }
        ex += c[u];
    }
    if (t == 0) g_off[N_NODES] = N_EDGES;
    __syncthreads();
    for (int e = t; e < N_EDGES; e += 1024) {
        int pos = atomicAdd(&scnt[ei[e]], 1);
        g_perm[pos] = e;
    }
}

// ---------------- hid = relu(edge_attr @ W1 + b1), fp16 output ----------------
#define HID_EB 8
__global__ void k_hid(const float* __restrict__ ea,
                      const float* __restrict__ W1,
                      const float* __restrict__ b1) {
    __shared__ float eaS[HID_EB][ED];
    int e0 = blockIdx.x * HID_EB;
    int tid = threadIdx.x;
    if (tid < HID_EB * ED) {
        int e = tid / ED, t = tid % ED;
        eaS[e][t] = ea[(size_t)(e0 + e) * ED + t];
    }
    __syncthreads();
    for (int k = tid; k < H2; k += 256) {
        float acc[HID_EB];
        float bv = b1[k];
#pragma unroll
        for (int e = 0; e < HID_EB; e++) acc[e] = bv;
#pragma unroll
        for (int t = 0; t < ED; t++) {
            float w = W1[t * H2 + k];
#pragma unroll
            for (int e = 0; e < HID_EB; e++) acc[e] = fmaf(eaS[e][t], w, acc[e]);
        }
#pragma unroll
        for (int e = 0; e < HID_EB; e++)
            g_hid[(size_t)(e0 + e) * H2 + k] = __float2half_rn(fmaxf(acc[e], 0.0f));
    }
}

// ---------------- GEMM1 (1-term fp16, mma.m16n8k16) ----------------
// M[n,c] = sum_j h[n,j]*W2flat[c*64+j], both operands fp16, fp32 accumulate.
// Tile 128 nodes x 128 cols, K=64. Fragment-ordered smem (1 LDS = 1 fragment).
// Vectorized fills: j and j+1 share a 4-byte smem word -> float2 load +
// one half2 store per pair (half the fill instructions).
//   BF[nt16][ks4][lane32] uint2 16 KB | AH[mt8][ks4][lane32] uint4 16 KB
// Epilogue restage needs 8 warps * 4352 B = 34816 B -> smem = max(32K, 34816).
#define OFF_BF 0
#define OFF_AH 16384
#define G1_SMEM 34816

__global__ void __launch_bounds__(256, 2) k_gemm1(const float* __restrict__ h,
                                                  const float* __restrict__ W2,
                                                  int n_base, int buf) {
    extern __shared__ __align__(16) char smdyn[];
    __half* Mout = buf ? g_MB : g_MA;
    int tid = threadIdx.x;
    int w = tid >> 5, lane = tid & 31;
    int n0 = n_base + blockIdx.y * 128;
    int rowloc0 = blockIdx.y * 128;
    size_t c0 = (size_t)blockIdx.x * 128;

    // ---- fill B fragments: 128 cols x 32 j-pairs ----
    for (int idx = tid; idx < 128 * 32; idx += 256) {
        int c = idx >> 5, jp = idx & 31;
        int j = jp * 2;
        float2 v = *(const float2*)&W2[(c0 + c) * 64 + j];
        int nt = c >> 3, colin = c & 7;
        int ks = j >> 4, kk = j & 15;
        int flane = colin * 4 + ((kk & 7) >> 1);
        int reg = kk >> 3;
        uint32_t off = (uint32_t)(((nt * 4 + ks) * 32 + flane) * 8 + reg * 4);
        *(__half2*)(smdyn + OFF_BF + off) = __floats2half2_rn(v.x, v.y);
    }
    // ---- fill A fragments: 128 nodes x 32 j-pairs ----
    for (int idx = tid; idx < 128 * 32; idx += 256) {
        int m = idx >> 5, jp = idx & 31;
        int j = jp * 2;
        int n = n0 + m;
        float2 v = (n < N_NODES) ? *(const float2*)&h[(size_t)n * 64 + j]
                                 : make_float2(0.f, 0.f);
        int mt = m >> 4, mm = m & 15;
        int ks = j >> 4, kk = j & 15;
        int flane = (mm & 7) * 4 + ((kk & 7) >> 1);
        int reg = (mm >> 3) | ((kk >> 3) << 1);
        uint32_t off = (uint32_t)(((mt * 4 + ks) * 32 + flane) * 16 + reg * 4);
        *(__half2*)(smdyn + OFF_AH + off) = __floats2half2_rn(v.x, v.y);
    }
    __syncthreads();

    // preload all A fragments for this warp's m-tile into registers
    uint4 aR[4];
#pragma unroll
    for (int ks = 0; ks < 4; ks++)
        aR[ks] = *(const uint4*)(smdyn + OFF_AH + ((w * 4 + ks) * 32 + lane) * 16);

    float acc[16][4];
#pragma unroll
    for (int nt = 0; nt < 16; nt++)
#pragma unroll
        for (int r = 0; r < 4; r++) acc[nt][r] = 0.0f;

#pragma unroll
    for (int ks = 0; ks < 4; ks++) {
#pragma unroll
        for (int nt = 0; nt < 16; nt++) {
            uint2 b = *(const uint2*)(smdyn + OFF_BF + ((nt * 4 + ks) * 32 + lane) * 8);
            mma_f16_k16(acc[nt], aR[ks].x, aR[ks].y, aR[ks].z, aR[ks].w, b.x, b.y);
        }
    }

    // ---- epilogue: fp16 convert, smem restage (pitch 272B), STG.128 ----
    __syncthreads();                       // all warps done reading fragments
    uint32_t wbase = (uint32_t)w * 4352;   // 16 rows * 272 B per warp
    int r = lane >> 2, cq = lane & 3;
#pragma unroll
    for (int nt = 0; nt < 16; nt++) {
        *(__half2*)(smdyn + wbase + r * 272 + nt * 16 + cq * 4) =
            __floats2half2_rn(acc[nt][0], acc[nt][1]);
        *(__half2*)(smdyn + wbase + (r + 8) * 272 + nt * 16 + cq * 4) =
            __floats2half2_rn(acc[nt][2], acc[nt][3]);
    }
    __syncwarp();
    int rr = lane >> 3, seg = lane & 7;
#pragma unroll
    for (int it = 0; it < 4; it++) {
#pragma unroll
        for (int j = 0; j < 2; j++) {
            int r2 = rr + it * 4;
            uint4 vv = *(const uint4*)(smdyn + wbase + r2 * 272 + (seg * 2 + j) * 16);
            int gr = rowloc0 + w * 16 + r2;       // local row in pass buffer
            size_t col = c0 + (size_t)(seg * 2 + j) * 8;
            __stcs((uint4*)(Mout + (size_t)gr * NCOLS + col), vv);
        }
    }
}

// ---------------- Stage 2: m[e,i] = sum_k hid[e,k]*M[n,k*64+i] + cb[i] ----------------
// Blocked edge mapping (warp s -> edges 3s..3s+2); raw fp16 Ms in smem.
#define S2_BODY(NACC)                                                         \
    _Pragma("unroll 4")                                                       \
    for (int k = 0; k < 128; k++) {                                           \
        float2 mm = __half22float2(((const __half2*)Ms)[k * 32 + il]);        \
        float h0 = hidS[e0s * 128 + k];                                       \
        a0.x = fmaf(h0, mm.x, a0.x);                                          \
        a0.y = fmaf(h0, mm.y, a0.y);                                          \
        if (NACC > 1) {                                                       \
            float h1 = hidS[(e0s + 1) * 128 + k];                             \
            a1.x = fmaf(h1, mm.x, a1.x);                                      \
            a1.y = fmaf(h1, mm.y, a1.y);                                      \
        }                                                                     \
        if (NACC > 2) {                                                       \
            float h2v = hidS[(e0s + 2) * 128 + k];                            \
            a2.x = fmaf(h2v, mm.x, a2.x);                                     \
            a2.y = fmaf(h2v, mm.y, a2.y);                                     \
        }                                                                     \
    }

__global__ void __launch_bounds__(256) k_stage2(const float* __restrict__ h,
                                                const float* __restrict__ b2,
                                                float* __restrict__ out,
                                                int n_base, int buf) {
    __shared__ __align__(16) __half Ms[128 * 64];     // 16 KB raw fp16 [k][i]
    __shared__ __align__(16) float hidS[24 * 128];    // 12 KB [slot24][k128]
    __shared__ float hS[64];
    __shared__ float cb[64];
    __shared__ int eS[24];

    int n = n_base + blockIdx.x;
    if (n >= N_NODES) return;
    int start = g_off[n], end = g_off[n + 1];
    if (start == end) return;

    const __half* Mbuf = buf ? g_MB : g_MA;

    int tid = threadIdx.x;
    int s = tid >> 5;
    int il = tid & 31;
    int i2 = il * 2;
    int e0s = 3 * s;          // first local edge owned by this warp

    if (tid < 64) hS[tid] = h[(size_t)n * 64 + tid];
    __syncthreads();
    if (s == 0) {
        float c0 = 0.f, c1 = 0.f;
#pragma unroll 8
        for (int j = 0; j < 64; j++) {
            float hv = hS[j];
            c0 = fmaf(b2[i2 * 64 + j], hv, c0);
            c1 = fmaf(b2[(i2 + 1) * 64 + j], hv, c1);
        }
        cb[i2] = c0; cb[i2 + 1] = c1;
    }

    const __half* Mrow = Mbuf + (size_t)(n - n_base) * NCOLS;

    for (int base = start; base < end; base += 24) {
        int cnt = min(24, end - base);
        __syncthreads();
        if (tid < cnt) eS[tid] = g_perm[base + tid];
        __syncthreads();

        float2 a0 = make_float2(cb[i2], cb[i2 + 1]);
        float2 a1 = a0, a2 = a0;
        int nacc = min(3, cnt - e0s);   // may be <=0 for idle warps

        for (int kc = 0; kc < 32; kc++) {
            __syncthreads();
            const uint4* msrc = (const uint4*)(Mrow + (size_t)kc * 8192);
            for (int u = tid; u < 1024; u += 256)
                ((uint4*)Ms)[u] = __ldcs(msrc + u);
            for (int u = tid; u < cnt * 32; u += 256) {
                int v = u >> 5, q = u & 31;
                const uint2* hsrc =
                    (const uint2*)(g_hid + (size_t)eS[v] * H2 + kc * 128);
                uint2 raw = __ldcs(hsrc + q);
                __half2* hp = (__half2*)&raw;
                float2 f0 = __half22float2(hp[0]);
                float2 f1 = __half22float2(hp[1]);
                ((float4*)(hidS + v * 128))[q] = make_float4(f0.x, f0.y, f1.x, f1.y);
            }
            __syncthreads();
            switch (nacc) {
                case 1: { S2_BODY(1) } break;
                case 2: { S2_BODY(2) } break;
                case 3: { S2_BODY(3) } break;
                default: break;
            }
        }
        if (nacc > 0) *(float2*)&out[(size_t)eS[e0s] * 64 + i2] = a0;
        if (nacc > 1) *(float2*)&out[(size_t)eS[e0s + 1] * 64 + i2] = a1;
        if (nacc > 2) *(float2*)&out[(size_t)eS[e0s + 2] * 64 + i2] = a2;
    }
}

// ---------------- dst passthrough ----------------
__global__ void k_dst(const int* __restrict__ ei, float* __restrict__ out) {
    int e = blockIdx.x * blockDim.x + threadIdx.x;
    if (e < N_EDGES) out[(size_t)N_EDGES * 64 + e] = (float)ei[N_EDGES + e];
}

// ---------------- launch: software pipeline across two captured streams ----
extern "C" void kernel_launch(void* const* d_in, const int* in_sizes, int n_in,
                              void* d_out, int out_size) {
    const float* h  = (const float*)d_in[0];
    const int*   ei = (const int*)d_in[1];
    const float* ea = (const float*)d_in[2];
    const float* W1 = (const float*)d_in[3];
    const float* b1 = (const float*)d_in[4];
    const float* W2 = (const float*)d_in[5];
    const float* b2 = (const float*)d_in[6];
    float* out = (float*)d_out;

    cudaFuncSetAttribute(k_gemm1, cudaFuncAttributeMaxDynamicSharedMemorySize,
                         G1_SMEM);

    // Fork a side stream into the capture (event-based, graph-capturable).
    // Created fresh per call (kernel_launch runs ~2x: correctness + capture);
    // intentionally not destroyed — destroying objects referenced by an
    // in-progress capture is UB, and the leak is a few host handles.
    cudaStream_t s2;
    cudaStreamCreateWithFlags(&s2, cudaStreamNonBlocking);
    cudaEvent_t evb;
    cudaEventCreateWithFlags(&evb, cudaEventDisableTiming);
    cudaEventRecord(evb, 0);
    cudaStreamWaitEvent(s2, evb, 0);

    // side stream: CSR + hid (independent of gemm; overlap gemm pass 0)
    k_csr<<<1, 1024, 0, s2>>>(ei);
    k_hid<<<N_EDGES / HID_EB, 256, 0, s2>>>(ea, W1, b1);

    cudaEvent_t ev_g[N_PASSES], ev_s[N_PASSES];
    for (int p = 0; p < N_PASSES; p++) {
        int n_base = p * PASS_NODES;
        int rem = N_NODES - n_base;
        int nodes = rem < PASS_NODES ? rem : PASS_NODES;
        int buf = p & 1;

        // buffer reuse hazard: gemm(p) overwrites buf used by stage2(p-2)
        if (p >= 2) cudaStreamWaitEvent(0, ev_s[p - 2], 0);

        dim3 g1(2048, (nodes + 127) / 128);
        k_gemm1<<<g1, 256, G1_SMEM, 0>>>(h, W2, n_base, buf);
        cudaEventCreateWithFlags(&ev_g[p], cudaEventDisableTiming);
        cudaEventRecord(ev_g[p], 0);

        cudaStreamWaitEvent(s2, ev_g[p], 0);
        k_stage2<<<nodes, 256, 0, s2>>>(h, b2, out, n_base, buf);
        cudaEventCreateWithFlags(&ev_s[p], cudaEventDisableTiming);
        cudaEventRecord(ev_s[p], s2);
    }

    // rejoin side stream into the origin stream before capture ends
    cudaStreamWaitEvent(0, ev_s[N_PASSES - 1], 0);

    if (out_size > N_EDGES * 64)
        k_dst<<<(N_EDGES + 255) / 256, 256, 0, 0>>>(ei, out);
}

// round 15
// speedup vs baseline: 1.9810x; 1.9810x over previous
#include <cuda_runtime.h>
#include <cuda_fp16.h>
#include <cstring>
#include <cstdint>

#define N_NODES 5000
#define N_EDGES 30000
#define HID     64
#define ED      16
#define H2      4096
#define NCOLS   262144       // 4096*64 columns of M

#define PASS_NODES 2048
#define N_PASSES   3         // ceil(5000/2048)
#define N_GROUPS   40        // ceil(5000/128) row groups of 128 nodes
#define N_CBLK     2048      // 262144/128 col blocks

// ---------------- static device scratch (no allocs; keep total < ~1.6 GB) ----
__device__ __align__(16) __half g_M[(size_t)PASS_NODES * NCOLS];   // 1.07 GB
__device__ __align__(16) __half g_hid[(size_t)N_EDGES * H2];       // 246 MB
// Pre-converted fragment-ordered operands (gemm fill = straight uint4 copy).
// B fragment block = 16*4*32 uint2 = 16384 B = 8192 halves (NOT 8192 B —
// that typo was round 14's corruption).
__device__ __align__(16) __half g_W2f[(size_t)N_CBLK * 8192];      // 33.5 MB
__device__ __align__(16) __half g_hf[(size_t)N_GROUPS * 8192];     // 640 KB

__device__ int g_off[N_NODES + 1];
__device__ int g_perm[N_EDGES];

// ---------------- fp16 mma (legacy path; tcgen05 rejected: harness PTX
// targets compute_100 without the 'a' feature set) ----------------
__device__ __forceinline__ void mma_f16_k16(float* c,
                                            uint32_t a0, uint32_t a1,
                                            uint32_t a2, uint32_t a3,
                                            uint32_t b0, uint32_t b1) {
    asm volatile(
        "mma.sync.aligned.m16n8k16.row.col.f32.f16.f16.f32 "
        "{%0,%1,%2,%3},{%4,%5,%6,%7},{%8,%9},{%0,%1,%2,%3};"
        : "+f"(c[0]), "+f"(c[1]), "+f"(c[2]), "+f"(c[3])
        : "r"(a0), "r"(a1), "r"(a2), "r"(a3), "r"(b0), "r"(b1));
}

// ---------------- fused single-block CSR build ----------------
__global__ void __launch_bounds__(1024) k_csr(const int* __restrict__ ei) {
    __shared__ int scnt[N_NODES];
    __shared__ int ts[1024];
    int t = threadIdx.x;

    for (int i = t; i < N_NODES; i += 1024) scnt[i] = 0;
    __syncthreads();
    for (int e = t; e < N_EDGES; e += 1024) atomicAdd(&scnt[ei[e]], 1);
    __syncthreads();

    int c[5];
    int base = t * 5;
    int s = 0;
#pragma unroll
    for (int u = 0; u < 5; u++) {
        int id = base + u;
        c[u] = (id < N_NODES) ? scnt[id] : 0;
        s += c[u];
    }
    ts[t] = s;
    __syncthreads();
    for (int ofs = 1; ofs < 1024; ofs <<= 1) {
        int v = (t >= ofs) ? ts[t - ofs] : 0;
        __syncthreads();
        ts[t] += v;
        __syncthreads();
    }
    int ex = ts[t] - s;
#pragma unroll
    for (int u = 0; u < 5; u++) {
        int id = base + u;
        if (id < N_NODES) { g_off[id] = ex; scnt[id] = ex; }
        ex += c[u];
    }
    if (t == 0) g_off[N_NODES] = N_EDGES;
    __syncthreads();
    for (int e = t; e < N_EDGES; e += 1024) {
        int pos = atomicAdd(&scnt[ei[e]], 1);
        g_perm[pos] = e;
    }
}

// ---------------- hid = relu(edge_attr @ W1 + b1), fp16 output ----------------
#define HID_EB 8
__global__ void k_hid(const float* __restrict__ ea,
                      const float* __restrict__ W1,
                      const float* __restrict__ b1) {
    __shared__ float eaS[HID_EB][ED];
    int e0 = blockIdx.x * HID_EB;
    int tid = threadIdx.x;
    if (tid < HID_EB * ED) {
        int e = tid / ED, t = tid % ED;
        eaS[e][t] = ea[(size_t)(e0 + e) * ED + t];
    }
    __syncthreads();
    for (int k = tid; k < H2; k += 256) {
        float acc[HID_EB];
        float bv = b1[k];
#pragma unroll
        for (int e = 0; e < HID_EB; e++) acc[e] = bv;
#pragma unroll
        for (int t = 0; t < ED; t++) {
            float w = W1[t * H2 + k];
#pragma unroll
            for (int e = 0; e < HID_EB; e++) acc[e] = fmaf(eaS[e][t], w, acc[e]);
        }
#pragma unroll
        for (int e = 0; e < HID_EB; e++)
            g_hid[(size_t)(e0 + e) * H2 + k] = __float2half_rn(fmaxf(acc[e], 0.0f));
    }
}

// ---------------- pre-convert W2 -> fragment-ordered fp16 blocks ----------------
// Block cb holds cols [cb*128, cb*128+128) x j[0,64) as
// BF[nt16][ks4][lane32] uint2(b0,b1) = 16384 bytes, exactly the smem layout.
__global__ void __launch_bounds__(256) k_w2frag(const float* __restrict__ W2) {
    int cb = blockIdx.x;
    size_t c0 = (size_t)cb * 128;
    char* dst = (char*)g_W2f + (size_t)cb * 16384;
    int tid = threadIdx.x;
    for (int idx = tid; idx < 128 * 32; idx += 256) {
        int c = idx >> 5, jp = idx & 31;
        int j = jp * 2;
        float2 v = *(const float2*)&W2[(c0 + c) * 64 + j];
        int nt = c >> 3, colin = c & 7;
        int ks = j >> 4, kk = j & 15;
        int flane = colin * 4 + ((kk & 7) >> 1);
        int reg = kk >> 3;
        uint32_t off = (uint32_t)(((nt * 4 + ks) * 32 + flane) * 8 + reg * 4);
        *(__half2*)(dst + off) = __floats2half2_rn(v.x, v.y);
    }
}

// ---------------- pre-convert h -> fragment-ordered fp16 row groups ----------------
// Group rg holds nodes [rg*128, rg*128+128) as AH[mt8][ks4][lane32] uint4 = 16384 B.
__global__ void __launch_bounds__(256) k_hfrag(const float* __restrict__ h) {
    int rg = blockIdx.x;
    int n0 = rg * 128;
    char* dst = (char*)g_hf + (size_t)rg * 16384;
    int tid = threadIdx.x;
    for (int idx = tid; idx < 128 * 32; idx += 256) {
        int m = idx >> 5, jp = idx & 31;
        int j = jp * 2;
        int n = n0 + m;
        float2 v = (n < N_NODES) ? *(const float2*)&h[(size_t)n * 64 + j]
                                 : make_float2(0.f, 0.f);
        int mt = m >> 4, mm = m & 15;
        int ks = j >> 4, kk = j & 15;
        int flane = (mm & 7) * 4 + ((kk & 7) >> 1);
        int reg = (mm >> 3) | ((kk >> 3) << 1);
        uint32_t off = (uint32_t)(((mt * 4 + ks) * 32 + flane) * 16 + reg * 4);
        *(__half2*)(dst + off) = __floats2half2_rn(v.x, v.y);
    }
}

// ---------------- GEMM1 (1-term fp16, mma.m16n8k16) ----------------
// M[n,c] = sum_j h[n,j]*W2flat[c*64+j]; operands pre-converted to fragment
// layout so the fills are pure uint4 copies.
//   BF 16 KB | AH 16 KB; epilogue restage needs 34816 B -> smem 34816.
#define OFF_BF 0
#define OFF_AH 16384
#define G1_SMEM 34816

__global__ void __launch_bounds__(256, 2) k_gemm1(int n_base) {
    extern __shared__ __align__(16) char smdyn[];
    int tid = threadIdx.x;
    int w = tid >> 5, lane = tid & 31;
    int rowloc0 = blockIdx.y * 128;
    int group = (n_base >> 7) + blockIdx.y;
    size_t c0 = (size_t)blockIdx.x * 128;

    // ---- fills: straight uint4 copies of pre-converted fragments ----
    {
        const uint4* bsrc = (const uint4*)((const char*)g_W2f + (size_t)blockIdx.x * 16384);
        uint4* bdst = (uint4*)(smdyn + OFF_BF);
#pragma unroll
        for (int u = 0; u < 4; u++) bdst[tid + 256 * u] = __ldg(bsrc + tid + 256 * u);
        const uint4* asrc = (const uint4*)((const char*)g_hf + (size_t)group * 16384);
        uint4* adst = (uint4*)(smdyn + OFF_AH);
#pragma unroll
        for (int u = 0; u < 4; u++) adst[tid + 256 * u] = __ldg(asrc + tid + 256 * u);
    }
    __syncthreads();

    // preload all A fragments for this warp's m-tile into registers
    uint4 aR[4];
#pragma unroll
    for (int ks = 0; ks < 4; ks++)
        aR[ks] = *(const uint4*)(smdyn + OFF_AH + ((w * 4 + ks) * 32 + lane) * 16);

    float acc[16][4];
#pragma unroll
    for (int nt = 0; nt < 16; nt++)
#pragma unroll
        for (int r = 0; r < 4; r++) acc[nt][r] = 0.0f;

#pragma unroll
    for (int ks = 0; ks < 4; ks++) {
#pragma unroll
        for (int nt = 0; nt < 16; nt++) {
            uint2 b = *(const uint2*)(smdyn + OFF_BF + ((nt * 4 + ks) * 32 + lane) * 8);
            mma_f16_k16(acc[nt], aR[ks].x, aR[ks].y, aR[ks].z, aR[ks].w, b.x, b.y);
        }
    }

    // ---- epilogue: fp16 convert, smem restage (pitch 272B), STG.128 ----
    __syncthreads();                       // all warps done reading fragments
    uint32_t wbase = (uint32_t)w * 4352;   // 16 rows * 272 B per warp
    int r = lane >> 2, cq = lane & 3;
#pragma unroll
    for (int nt = 0; nt < 16; nt++) {
        *(__half2*)(smdyn + wbase + r * 272 + nt * 16 + cq * 4) =
            __floats2half2_rn(acc[nt][0], acc[nt][1]);
        *(__half2*)(smdyn + wbase + (r + 8) * 272 + nt * 16 + cq * 4) =
            __floats2half2_rn(acc[nt][2], acc[nt][3]);
    }
    __syncwarp();
    int rr = lane >> 3, seg = lane & 7;
#pragma unroll
    for (int it = 0; it < 4; it++) {
#pragma unroll
        for (int j = 0; j < 2; j++) {
            int r2 = rr + it * 4;
            uint4 vv = *(const uint4*)(smdyn + wbase + r2 * 272 + (seg * 2 + j) * 16);
            int gr = rowloc0 + w * 16 + r2;       // local row in pass buffer
            size_t col = c0 + (size_t)(seg * 2 + j) * 8;
            __stcs((uint4*)(g_M + (size_t)gr * NCOLS + col), vv);
        }
    }
}

// ---------------- Stage 2: m[e,i] = sum_k hid[e,k]*M[n,k*64+i] + cb[i] ----------------
// Blocked edge mapping (warp s -> edges 3s..3s+2); raw fp16 Ms in smem.
#define S2_BODY(NACC)                                                         \
    _Pragma("unroll 4")                                                       \
    for (int k = 0; k < 128; k++) {                                           \
        float2 mm = __half22float2(((const __half2*)Ms)[k * 32 + il]);        \
        float h0 = hidS[e0s * 128 + k];                                       \
        a0.x = fmaf(h0, mm.x, a0.x);                                          \
        a0.y = fmaf(h0, mm.y, a0.y);                                          \
        if (NACC > 1) {                                                       \
            float h1 = hidS[(e0s + 1) * 128 + k];                             \
            a1.x = fmaf(h1, mm.x, a1.x);                                      \
            a1.y = fmaf(h1, mm.y, a1.y);                                      \
        }                                                                     \
        if (NACC > 2) {                                                       \
            float h2v = hidS[(e0s + 2) * 128 + k];                            \
            a2.x = fmaf(h2v, mm.x, a2.x);                                     \
            a2.y = fmaf(h2v, mm.y, a2.y);                                     \
        }                                                                     \
    }

__global__ void __launch_bounds__(256) k_stage2(const float* __restrict__ h,
                                                const float* __restrict__ b2,
                                                float* __restrict__ out,
                                                int n_base) {
    __shared__ __align__(16) __half Ms[128 * 64];     // 16 KB raw fp16 [k][i]
    __shared__ __align__(16) float hidS[24 * 128];    // 12 KB [slot24][k128]
    __shared__ float hS[64];
    __shared__ float cb[64];
    __shared__ int eS[24];

    int n = n_base + blockIdx.x;
    if (n >= N_NODES) return;
    int start = g_off[n], end = g_off[n + 1];
    if (start == end) return;

    int tid = threadIdx.x;
    int s = tid >> 5;
    int il = tid & 31;
    int i2 = il * 2;
    int e0s = 3 * s;          // first local edge owned by this warp

    if (tid < 64) hS[tid] = h[(size_t)n * 64 + tid];
    __syncthreads();
    if (s == 0) {
        float c0 = 0.f, c1 = 0.f;
#pragma unroll 8
        for (int j = 0; j < 64; j++) {
            float hv = hS[j];
            c0 = fmaf(b2[i2 * 64 + j], hv, c0);
            c1 = fmaf(b2[(i2 + 1) * 64 + j], hv, c1);
        }
        cb[i2] = c0; cb[i2 + 1] = c1;
    }

    const __half* Mrow = g_M + (size_t)(n - n_base) * NCOLS;

    for (int base = start; base < end; base += 24) {
        int cnt = min(24, end - base);
        __syncthreads();
        if (tid < cnt) eS[tid] = g_perm[base + tid];
        __syncthreads();

        float2 a0 = make_float2(cb[i2], cb[i2 + 1]);
        float2 a1 = a0, a2 = a0;
        int nacc = min(3, cnt - e0s);   // may be <=0 for idle warps

        for (int kc = 0; kc < 32; kc++) {
            __syncthreads();
            const uint4* msrc = (const uint4*)(Mrow + (size_t)kc * 8192);
            for (int u = tid; u < 1024; u += 256)
                ((uint4*)Ms)[u] = __ldcs(msrc + u);
            for (int u = tid; u < cnt * 32; u += 256) {
                int v = u >> 5, q = u & 31;
                const uint2* hsrc =
                    (const uint2*)(g_hid + (size_t)eS[v] * H2 + kc * 128);
                uint2 raw = __ldcs(hsrc + q);
                __half2* hp = (__half2*)&raw;
                float2 f0 = __half22float2(hp[0]);
                float2 f1 = __half22float2(hp[1]);
                ((float4*)(hidS + v * 128))[q] = make_float4(f0.x, f0.y, f1.x, f1.y);
            }
            __syncthreads();
            switch (nacc) {
                case 1: { S2_BODY(1) } break;
                case 2: { S2_BODY(2) } break;
                case 3: { S2_BODY(3) } break;
                default: break;
            }
        }
        if (nacc > 0) *(float2*)&out[(size_t)eS[e0s] * 64 + i2] = a0;
        if (nacc > 1) *(float2*)&out[(size_t)eS[e0s + 1] * 64 + i2] = a1;
        if (nacc > 2) *(float2*)&out[(size_t)eS[e0s + 2] * 64 + i2] = a2;
    }
}

// ---------------- dst passthrough ----------------
__global__ void k_dst(const int* __restrict__ ei, float* __restrict__ out) {
    int e = blockIdx.x * blockDim.x + threadIdx.x;
    if (e < N_EDGES) out[(size_t)N_EDGES * 64 + e] = (float)ei[N_EDGES + e];
}

// ---------------- launch ----------------
extern "C" void kernel_launch(void* const* d_in, const int* in_sizes, int n_in,
                              void* d_out, int out_size) {
    const float* h  = (const float*)d_in[0];
    const int*   ei = (const int*)d_in[1];
    const float* ea = (const float*)d_in[2];
    const float* W1 = (const float*)d_in[3];
    const float* b1 = (const float*)d_in[4];
    const float* W2 = (const float*)d_in[5];
    const float* b2 = (const float*)d_in[6];
    float* out = (float*)d_out;

    k_csr<<<1, 1024>>>(ei);
    k_hid<<<N_EDGES / HID_EB, 256>>>(ea, W1, b1);
    k_w2frag<<<N_CBLK, 256>>>(W2);
    k_hfrag<<<N_GROUPS, 256>>>(h);

    cudaFuncSetAttribute(k_gemm1, cudaFuncAttributeMaxDynamicSharedMemorySize,
                         G1_SMEM);

    for (int p = 0; p < N_PASSES; p++) {
        int n_base = p * PASS_NODES;
        int rem = N_NODES - n_base;
        int nodes = rem < PASS_NODES ? rem : PASS_NODES;
        dim3 g1(N_CBLK, (nodes + 127) / 128);    // col-blocks x row-groups
        k_gemm1<<<g1, 256, G1_SMEM>>>(n_base);
        k_stage2<<<nodes, 256>>>(h, b2, out, n_base);
    }

    if (out_size > N_EDGES * 64)
        k_dst<<<(N_EDGES + 255) / 256, 256>>>(ei, out);
}